// round 15
// baseline (speedup 1.0000x reference)
#include <cuda_runtime.h>
#include <cuda_fp16.h>
#include <math.h>
#include <stdint.h>

#define S_LEN  2048
#define HID    2048
#define NHEADS 16
#define HS     128
#define QKV_N  6144
#define KTOT   2048
#define INV_NORM 0.08838834764831845f

// ---------------- scratch (device globals; no allocations allowed) ----------
__device__ __half g_A[(size_t)S_LEN * HID];
__device__ __half g_Bq[(size_t)QKV_N * HID];
__device__ __half g_Bo[(size_t)HID * HID];
__device__ __half g_AT[(size_t)S_LEN * HID];
__device__ __half g_Qq[(size_t)NHEADS * S_LEN * HS];
__device__ __half g_Kk[(size_t)NHEADS * S_LEN * HS];
__device__ __half g_Vv[(size_t)NHEADS * S_LEN * HS];

__device__ __constant__ float c_invfreq[16] = {
    1.0f, 0.5623413251903491f, 0.31622776601683794f, 0.17782794100389228f,
    0.1f, 0.05623413251903491f, 0.03162277660168379f, 0.017782794100389228f,
    0.01f, 0.005623413251903491f, 0.0031622776601683794f, 0.0017782794100389228f,
    0.001f, 0.0005623413251903491f, 0.00031622776601683794f, 0.00017782794100389228f
};

// ------------------------------- helpers ------------------------------------
__device__ __forceinline__ uint32_t smem_to_u32(const void* p) {
    uint32_t a;
    asm("{ .reg .u64 t; cvta.to.shared.u64 t, %1; cvt.u32.u64 %0, t; }"
        : "=r"(a) : "l"(p));
    return a;
}
__device__ __forceinline__ void cp_async16(uint32_t dst, const void* src) {
    asm volatile("cp.async.cg.shared.global [%0], [%1], 16;"
                 :: "r"(dst), "l"(src) : "memory");
}
#define CP_COMMIT() asm volatile("cp.async.commit_group;" ::: "memory")
#define CP_WAIT(n)  asm volatile("cp.async.wait_group %0;" :: "n"(n) : "memory")

__device__ __forceinline__ void mma_f16(float* c, const uint32_t* a, const uint32_t* b) {
    asm volatile(
        "mma.sync.aligned.m16n8k16.row.col.f32.f16.f16.f32 "
        "{%0,%1,%2,%3}, {%4,%5,%6,%7}, {%8,%9}, {%0,%1,%2,%3};"
        : "+f"(c[0]), "+f"(c[1]), "+f"(c[2]), "+f"(c[3])
        : "r"(a[0]), "r"(a[1]), "r"(a[2]), "r"(a[3]), "r"(b[0]), "r"(b[1]));
}
__device__ __forceinline__ void ldsm4(uint32_t& r0, uint32_t& r1, uint32_t& r2,
                                      uint32_t& r3, uint32_t addr) {
    asm volatile("ldmatrix.sync.aligned.m8n8.x4.shared.b16 {%0,%1,%2,%3}, [%4];"
        : "=r"(r0), "=r"(r1), "=r"(r2), "=r"(r3) : "r"(addr));
}
__device__ __forceinline__ void ldsm4t(uint32_t& r0, uint32_t& r1, uint32_t& r2,
                                       uint32_t& r3, uint32_t addr) {
    asm volatile("ldmatrix.sync.aligned.m8n8.x4.trans.shared.b16 {%0,%1,%2,%3}, [%4];"
        : "=r"(r0), "=r"(r1), "=r"(r2), "=r"(r3) : "r"(addr));
}
__device__ __forceinline__ uint32_t packh(float lo, float hi) {
    uint32_t d;
    asm("cvt.rn.f16x2.f32 %0, %1, %2;" : "=r"(d) : "f"(hi), "f"(lo));
    return d;
}

// epilogue store for mode 0 (QKV): fused rotary + fp16 Q/K/V scatter.
__device__ __forceinline__ void qkv_store(const float (*accw)[4], int i, int j,
                                          int half, int m, int n, float2 v,
                                          const float* bias)
{
    int h = n / 384, e = n - h * 384;
    int seg = e >> 7, d = e & 127;
    if (seg < 2 && d < 32) {
        bool low = d < 16;
        int jp = low ? j + 2 : j - 2;
        int np = low ? n + 16 : n - 16;
        float2 bvp = *reinterpret_cast<const float2*>(bias + np);
        float px = accw[jp][half * 2] + bvp.x;
        float py = accw[jp][half * 2 + 1] + bvp.y;
        float f0 = (float)m * c_invfreq[d & 15];
        float f1 = (float)m * c_invfreq[(d + 1) & 15];
        float s0, c0, s1, c1;
        sincosf(f0, &s0, &c0);
        sincosf(f1, &s1, &c1);
        if (low) { v.x = v.x * c0 - px * s0; v.y = v.y * c1 - py * s1; }
        else     { v.x = v.x * c0 + px * s0; v.y = v.y * c1 + py * s1; }
    }
    size_t off = ((size_t)h * S_LEN + m) * HS + d;
    uint32_t hp = packh(v.x, v.y);
    if (seg == 0)      *reinterpret_cast<uint32_t*>(g_Qq + off) = hp;
    else if (seg == 1) *reinterpret_cast<uint32_t*>(g_Kk + off) = hp;
    else               *reinterpret_cast<uint32_t*>(g_Vv + off) = hp;
}

// ---------------------------------------------------------------------------
// Conversion kernels
// ---------------------------------------------------------------------------
__global__ __launch_bounds__(256) void conv_h(
    const float4* __restrict__ X, __half2* __restrict__ H)
{
    int i = blockIdx.x * 256 + threadIdx.x;
    float4 v = X[i];
    H[2 * i]     = __halves2half2(__float2half_rn(v.x), __float2half_rn(v.y));
    H[2 * i + 1] = __halves2half2(__float2half_rn(v.z), __float2half_rn(v.w));
}

__global__ __launch_bounds__(256) void conv_transpose_h(
    const float* __restrict__ B, __half* __restrict__ H, int K, int N)
{
    __shared__ float t[32][33];
    int x = threadIdx.x & 31, y = threadIdx.x >> 5;
    int n0 = blockIdx.x * 32, k0 = blockIdx.y * 32;
#pragma unroll
    for (int j = 0; j < 32; j += 8)
        t[y + j][x] = B[(size_t)(k0 + y + j) * N + n0 + x];
    __syncthreads();
#pragma unroll
    for (int j = 0; j < 32; j += 8)
        H[(size_t)(n0 + y + j) * K + k0 + x] = __float2half_rn(t[x][y + j]);
}

// ---------------------------------------------------------------------------
// Shared GEMM constants (BK=32, 3-stage, ROWSTR=40)
// ---------------------------------------------------------------------------
#define GBK 32
#define GNITER (KTOT / GBK)          // 64
#define ROWSTR 40

// ============ QKV GEMM: 256 threads, BM=128, BN=256, 2 CTAs/SM =============
#define QA_BUFH (128 * ROWSTR)       // 5120 halves
#define QB_BUFH (256 * ROWSTR)       // 10240 halves
#define QST_A 0
#define QST_B QA_BUFH
#define QSTGH (QA_BUFH + QB_BUFH)    // 15360 halves = 30720 B
#define QGEMM_SMEM (3 * QSTGH * 2)   // 92160 B

__global__ __launch_bounds__(256, 2) void gemm_qkv(
    const __half* __restrict__ A, const __half* __restrict__ Bw,
    const float* __restrict__ bias)
{
    extern __shared__ __align__(16) __half sm[];
    const int tid = threadIdx.x;
    const int wid = tid >> 5, lane = tid & 31;
    const int wm = wid >> 2, wn = wid & 3;           // 2 x 4 warp grid
    const int n0 = blockIdx.x * 256, m0 = blockIdx.y * 128;
    const uint32_t sbase = smem_to_u32(sm);

    const int r  = lane >> 2;
    const int c2 = (lane & 3) * 2;
    const int arow = ((lane >> 3) & 1) * 8 + (lane & 7);
    const int acol = (lane >> 4) * 8;
    const int brow = ((lane >> 4) & 1) * 8 + (lane & 7);
    const int bcol = ((lane >> 3) & 1) * 8;

    float acc[4][8][4];
#pragma unroll
    for (int i = 0; i < 4; i++)
#pragma unroll
        for (int j = 0; j < 8; j++)
#pragma unroll
            for (int q = 0; q < 4; q++) acc[i][j][q] = 0.f;

    auto load_stage = [&](int s, int k0) {
        const uint32_t st = sbase + (uint32_t)s * QSTGH * 2;
#pragma unroll
        for (int i = 0; i < 2; i++) {               // A: 512 chunks / 256 thr
            int c = tid + i * 256;
            int row = c >> 2, kc = c & 3;
            uint32_t doff = (uint32_t)(row * ROWSTR + kc * 8) * 2;
            cp_async16(st + QST_A * 2 + doff,
                       A + (size_t)(m0 + row) * KTOT + k0 + kc * 8);
        }
#pragma unroll
        for (int i = 0; i < 4; i++) {               // B: 1024 chunks
            int c = tid + i * 256;
            int row = c >> 2, kc = c & 3;
            uint32_t doff = (uint32_t)(row * ROWSTR + kc * 8) * 2;
            cp_async16(st + QST_B * 2 + doff,
                       Bw + (size_t)(n0 + row) * KTOT + k0 + kc * 8);
        }
    };

    load_stage(0, 0); CP_COMMIT();
    load_stage(1, GBK); CP_COMMIT();

    for (int it = 0; it < GNITER; it++) {
        const int s = it % 3;
        if (it < GNITER - 1) { CP_WAIT(1); } else { CP_WAIT(0); }
        __syncthreads();

        const uint32_t stg = sbase + (uint32_t)s * QSTGH * 2;

#pragma unroll
        for (int ks = 0; ks < 2; ks++) {
            uint32_t ah[4][4], bh[8][2];
#pragma unroll
            for (int i = 0; i < 4; i++) {
                uint32_t a = stg + QST_A * 2
                           + (uint32_t)((wm * 64 + i * 16 + arow) * ROWSTR
                                        + ks * 16 + acol) * 2;
                ldsm4(ah[i][0], ah[i][1], ah[i][2], ah[i][3], a);
            }
#pragma unroll
            for (int jp = 0; jp < 4; jp++) {
                uint32_t b = stg + QST_B * 2
                           + (uint32_t)((wn * 64 + jp * 16 + brow) * ROWSTR
                                        + ks * 16 + bcol) * 2;
                ldsm4(bh[jp * 2][0], bh[jp * 2][1],
                      bh[jp * 2 + 1][0], bh[jp * 2 + 1][1], b);
            }
#pragma unroll
            for (int i = 0; i < 4; i++)
#pragma unroll
                for (int j = 0; j < 8; j++) mma_f16(acc[i][j], ah[i], bh[j]);
        }
        if (it + 2 < GNITER) {
            load_stage((it + 2) % 3, (it + 2) * GBK);
            CP_COMMIT();
        }
    }

#pragma unroll
    for (int i = 0; i < 4; i++) {
#pragma unroll
        for (int j = 0; j < 8; j++) {
            int n = n0 + wn * 64 + j * 8 + c2;
            float2 bv = *reinterpret_cast<const float2*>(bias + n);
#pragma unroll
            for (int half = 0; half < 2; half++) {
                int m = m0 + wm * 64 + i * 16 + r + half * 8;
                float2 v = make_float2(acc[i][j][half * 2] + bv.x,
                                       acc[i][j][half * 2 + 1] + bv.y);
                qkv_store(acc[i], i, j, half, m, n, v, bias);
            }
        }
    }
}

// ============ out-proj GEMM: 128 threads, BM=64, BN=256 (R13 config) ========
#define A_BUFH (64 * ROWSTR)
#define B_BUFH (256 * ROWSTR)
#define ST_A 0
#define ST_B A_BUFH
#define STGH  (A_BUFH + B_BUFH)
#define GEMM_SMEM (3 * STGH * 2)     // 76800 B

__global__ __launch_bounds__(128, 2) void gemm_out(
    const __half* __restrict__ A, const __half* __restrict__ Bw,
    const float* __restrict__ bias, int N, float* __restrict__ Cout)
{
    extern __shared__ __align__(16) __half sm[];
    const int tid = threadIdx.x;
    const int wn = tid >> 5, lane = tid & 31;
    const int n0 = blockIdx.x * 256, m0 = blockIdx.y * 64;
    const uint32_t sbase = smem_to_u32(sm);

    const int r  = lane >> 2;
    const int c2 = (lane & 3) * 2;
    const int arow = ((lane >> 3) & 1) * 8 + (lane & 7);
    const int acol = (lane >> 4) * 8;
    const int brow = ((lane >> 4) & 1) * 8 + (lane & 7);
    const int bcol = ((lane >> 3) & 1) * 8;

    float acc[4][8][4];
#pragma unroll
    for (int i = 0; i < 4; i++)
#pragma unroll
        for (int j = 0; j < 8; j++)
#pragma unroll
            for (int q = 0; q < 4; q++) acc[i][j][q] = 0.f;

    auto load_stage = [&](int s, int k0) {
        const uint32_t st = sbase + (uint32_t)s * STGH * 2;
#pragma unroll
        for (int i = 0; i < 2; i++) {
            int c = tid + i * 128;
            int row = c >> 2, kc = c & 3;
            uint32_t doff = (uint32_t)(row * ROWSTR + kc * 8) * 2;
            cp_async16(st + ST_A * 2 + doff,
                       A + (size_t)(m0 + row) * KTOT + k0 + kc * 8);
        }
#pragma unroll
        for (int i = 0; i < 8; i++) {
            int c = tid + i * 128;
            int row = c >> 2, kc = c & 3;
            uint32_t doff = (uint32_t)(row * ROWSTR + kc * 8) * 2;
            cp_async16(st + ST_B * 2 + doff,
                       Bw + (size_t)(n0 + row) * KTOT + k0 + kc * 8);
        }
    };

    load_stage(0, 0); CP_COMMIT();
    load_stage(1, GBK); CP_COMMIT();

    for (int it = 0; it < GNITER; it++) {
        const int s = it % 3;
        if (it < GNITER - 1) { CP_WAIT(1); } else { CP_WAIT(0); }
        __syncthreads();

        const uint32_t stg = sbase + (uint32_t)s * STGH * 2;

#pragma unroll
        for (int ks = 0; ks < 2; ks++) {
            uint32_t ah[4][4], bh[8][2];
#pragma unroll
            for (int i = 0; i < 4; i++) {
                uint32_t a = stg + ST_A * 2
                           + (uint32_t)((i * 16 + arow) * ROWSTR + ks * 16 + acol) * 2;
                ldsm4(ah[i][0], ah[i][1], ah[i][2], ah[i][3], a);
            }
#pragma unroll
            for (int jp = 0; jp < 4; jp++) {
                uint32_t b = stg + ST_B * 2
                           + (uint32_t)((wn * 64 + jp * 16 + brow) * ROWSTR
                                        + ks * 16 + bcol) * 2;
                ldsm4(bh[jp * 2][0], bh[jp * 2][1],
                      bh[jp * 2 + 1][0], bh[jp * 2 + 1][1], b);
            }
#pragma unroll
            for (int i = 0; i < 4; i++)
#pragma unroll
                for (int j = 0; j < 8; j++) mma_f16(acc[i][j], ah[i], bh[j]);
        }
        if (it + 2 < GNITER) {
            load_stage((it + 2) % 3, (it + 2) * GBK);
            CP_COMMIT();
        }
    }

#pragma unroll
    for (int i = 0; i < 4; i++) {
#pragma unroll
        for (int j = 0; j < 8; j++) {
            int n = n0 + wn * 64 + j * 8 + c2;
            float2 bv = *reinterpret_cast<const float2*>(bias + n);
#pragma unroll
            for (int half = 0; half < 2; half++) {
                int m = m0 + i * 16 + r + half * 8;
                float2 v = make_float2(acc[i][j][half * 2] + bv.x,
                                       acc[i][j][half * 2 + 1] + bv.y);
                *reinterpret_cast<float2*>(Cout + (size_t)m * N + n) = v;
            }
        }
    }
}

// ---------------------------------------------------------------------------
// Flash attention, plain fp16 mma.sync (unchanged from R13).
// ---------------------------------------------------------------------------
#define KSTR 136
#define SM_K 0
#define SM_V (64 * KSTR)
#define FLASH_SMEM (2 * 64 * KSTR * 2)

__global__ __launch_bounds__(128, 2) void flash_mma()
{
    const int h  = blockIdx.y;
    const int qt = (gridDim.x - 1) - blockIdx.x;
    const int q0 = qt * 64;

    extern __shared__ __align__(16) __half fsm[];
    const uint32_t sbase = smem_to_u32(fsm);

    const int tid = threadIdx.x;
    const int w = tid >> 5, lane = tid & 31;
    const int r = lane >> 2, c2 = (lane & 3) * 2;
    const int brow = ((lane >> 4) & 1) * 8 + (lane & 7);
    const int bcol = ((lane >> 3) & 1) * 8;
    const int trow = lane & 15;
    const int tcol = ((lane >> 4) & 1) * 8;
    const int qrow = q0 + w * 16 + r;

    const __half* Qg = g_Qq + (size_t)h * S_LEN * HS;
    const __half* Kg = g_Kk + (size_t)h * S_LEN * HS;
    const __half* Vg = g_Vv + (size_t)h * S_LEN * HS;

    auto load_K = [&](int kt) {
        const int kb0 = kt * 64;
#pragma unroll
        for (int i = 0; i < 8; i++) {
            int c = i * 128 + tid;
            int row = c >> 4, col = c & 15;
            cp_async16(sbase + SM_K * 2 + (uint32_t)(row * KSTR + col * 8) * 2,
                       Kg + (size_t)(kb0 + row) * HS + col * 8);
        }
    };
    auto load_V = [&](int kt) {
        const int kb0 = kt * 64;
#pragma unroll
        for (int i = 0; i < 8; i++) {
            int c = i * 128 + tid;
            int row = c >> 4, col = c & 15;
            cp_async16(sbase + SM_V * 2 + (uint32_t)(row * KSTR + col * 8) * 2,
                       Vg + (size_t)(kb0 + row) * HS + col * 8);
        }
    };

    uint32_t qh[8][4];
#pragma unroll
    for (int kc = 0; kc < 8; kc++) {
        size_t o0 = (size_t)qrow * HS + kc * 16 + c2;
        size_t o1 = (size_t)(qrow + 8) * HS + kc * 16 + c2;
        qh[kc][0] = *reinterpret_cast<const uint32_t*>(Qg + o0);
        qh[kc][1] = *reinterpret_cast<const uint32_t*>(Qg + o1);
        qh[kc][2] = *reinterpret_cast<const uint32_t*>(Qg + o0 + 8);
        qh[kc][3] = *reinterpret_cast<const uint32_t*>(Qg + o1 + 8);
    }

    load_K(0); CP_COMMIT();
    load_V(0); CP_COMMIT();

    float o[16][4];
#pragma unroll
    for (int t = 0; t < 16; t++)
#pragma unroll
        for (int q = 0; q < 4; q++) o[t][q] = 0.f;
    float m2[2] = {-1e30f, -1e30f};
    float l[2] = {0.f, 0.f};

    const float SC = INV_NORM * 1.4426950408889634f;

    for (int kt = 0; kt <= qt; kt++) {
        const int kb0 = kt * 64;
        CP_WAIT(1);
        __syncthreads();

        float sacc[8][4];
#pragma unroll
        for (int j = 0; j < 8; j++)
#pragma unroll
            for (int q = 0; q < 4; q++) sacc[j][q] = 0.f;
#pragma unroll
        for (int kc = 0; kc < 8; kc++) {
#pragma unroll
            for (int jh = 0; jh < 2; jh++) {
                uint32_t bh[4][2];
#pragma unroll
                for (int jp = 0; jp < 2; jp++) {
                    uint32_t a = sbase + SM_K * 2
                        + (uint32_t)(((jh * 4 + jp * 2) * 8 + brow) * KSTR
                                     + kc * 16 + bcol) * 2;
                    ldsm4(bh[jp * 2][0], bh[jp * 2][1],
                          bh[jp * 2 + 1][0], bh[jp * 2 + 1][1], a);
                }
#pragma unroll
                for (int jj = 0; jj < 4; jj++) mma_f16(sacc[jh * 4 + jj], qh[kc], bh[jj]);
            }
        }

        if (kt == qt) {
#pragma unroll
            for (int j = 0; j < 8; j++) {
#pragma unroll
                for (int q = 0; q < 4; q++) {
                    int col = kb0 + j * 8 + c2 + (q & 1);
                    int row = qrow + ((q >= 2) ? 8 : 0);
                    if (col > row) sacc[j][q] = -1e30f;
                }
            }
        }

#pragma unroll
        for (int g = 0; g < 2; g++) {
            float rm = -1e30f;
#pragma unroll
            for (int j = 0; j < 8; j++)
                rm = fmaxf(rm, fmaxf(sacc[j][2 * g], sacc[j][2 * g + 1]));
            rm *= SC;
            rm = fmaxf(rm, __shfl_xor_sync(0xffffffffu, rm, 1));
            rm = fmaxf(rm, __shfl_xor_sync(0xffffffffu, rm, 2));
            float mn = fmaxf(m2[g], rm);
            float alpha = exp2f(m2[g] - mn);
            m2[g] = mn;
            float rs = 0.f;
#pragma unroll
            for (int j = 0; j < 8; j++) {
#pragma unroll
                for (int q = 2 * g; q < 2 * g + 2; q++) {
                    float p = exp2f(sacc[j][q] * SC - mn);
                    sacc[j][q] = p;
                    rs += p;
                }
            }
            rs += __shfl_xor_sync(0xffffffffu, rs, 1);
            rs += __shfl_xor_sync(0xffffffffu, rs, 2);
            l[g] = l[g] * alpha + rs;
#pragma unroll
            for (int t = 0; t < 16; t++) {
                o[t][2 * g]     *= alpha;
                o[t][2 * g + 1] *= alpha;
            }
        }

        __syncthreads();
        const bool more = (kt + 1 <= qt);
        if (more) { load_K(kt + 1); CP_COMMIT(); CP_WAIT(1); }
        else      { CP_WAIT(0); }
        __syncthreads();

#pragma unroll
        for (int kc2 = 0; kc2 < 4; kc2++) {
            uint32_t ph[4];
            ph[0] = packh(sacc[2 * kc2][0], sacc[2 * kc2][1]);
            ph[1] = packh(sacc[2 * kc2][2], sacc[2 * kc2][3]);
            ph[2] = packh(sacc[2 * kc2 + 1][0], sacc[2 * kc2 + 1][1]);
            ph[3] = packh(sacc[2 * kc2 + 1][2], sacc[2 * kc2 + 1][3]);
#pragma unroll
            for (int jg = 0; jg < 8; jg++) {
                uint32_t a = sbase + SM_V * 2
                    + (uint32_t)((kc2 * 16 + trow) * KSTR + jg * 16 + tcol) * 2;
                uint32_t vh[2][2];
                ldsm4t(vh[0][0], vh[0][1], vh[1][0], vh[1][1], a);
#pragma unroll
                for (int jj = 0; jj < 2; jj++) mma_f16(o[jg * 2 + jj], ph, vh[jj]);
            }
        }

        if (more) {
            __syncthreads();
            load_V(kt + 1); CP_COMMIT();
        }
    }

    float inv0 = 1.f / l[0], inv1 = 1.f / l[1];
#pragma unroll
    for (int jd = 0; jd < 16; jd++) {
        int col = h * HS + jd * 8 + c2;
        *reinterpret_cast<uint32_t*>(g_AT + (size_t)qrow * HID + col) =
            packh(o[jd][0] * inv0, o[jd][1] * inv0);
        *reinterpret_cast<uint32_t*>(g_AT + (size_t)(qrow + 8) * HID + col) =
            packh(o[jd][2] * inv1, o[jd][3] * inv1);
    }
}

// ---------------------------------------------------------------------------
extern "C" void kernel_launch(void* const* d_in, const int* in_sizes, int n_in,
                              void* d_out, int out_size)
{
    (void)in_sizes; (void)n_in; (void)out_size;
    const float* hidden = (const float*)d_in[0];
    const float* qkvk = (const float*)d_in[2];
    const float* qkvb = (const float*)d_in[3];
    const float* outk = (const float*)d_in[4];
    const float* outb = (const float*)d_in[5];
    float* out = (float*)d_out;

    cudaFuncSetAttribute(gemm_qkv, cudaFuncAttributeMaxDynamicSharedMemorySize, QGEMM_SMEM);
    cudaFuncSetAttribute(gemm_out, cudaFuncAttributeMaxDynamicSharedMemorySize, GEMM_SMEM);
    cudaFuncSetAttribute(flash_mma, cudaFuncAttributeMaxDynamicSharedMemorySize, FLASH_SMEM);

    void *A, *Bq, *Bo, *AT;
    cudaGetSymbolAddress(&A, g_A);
    cudaGetSymbolAddress(&Bq, g_Bq);   cudaGetSymbolAddress(&Bo, g_Bo);
    cudaGetSymbolAddress(&AT, g_AT);

    conv_h<<<(S_LEN * HID) / 1024, 256>>>((const float4*)hidden, (__half2*)A);
    conv_transpose_h<<<dim3(QKV_N / 32, HID / 32), 256>>>(
        qkvk, (__half*)Bq, HID, QKV_N);
    conv_transpose_h<<<dim3(HID / 32, HID / 32), 256>>>(
        outk, (__half*)Bo, HID, HID);

    // QKV projection + fused rotary; 256-thread CTAs, 4 warps/SMSP
    gemm_qkv<<<dim3(QKV_N / 256, S_LEN / 128), 256, QGEMM_SMEM>>>(
        (const __half*)A, (const __half*)Bq, qkvb);

    // causal flash attention
    flash_mma<<<dim3(S_LEN / 64, NHEADS), 128, FLASH_SMEM>>>();

    // output projection (128-thread CTAs for grid parallelism)
    gemm_out<<<dim3(HID / 256, S_LEN / 64), 128, GEMM_SMEM>>>(
        (const __half*)AT, (const __half*)Bo, outb, HID, out);
}

// round 16
// speedup vs baseline: 1.7081x; 1.7081x over previous
#include <cuda_runtime.h>
#include <cuda_fp16.h>
#include <math.h>
#include <stdint.h>

#define S_LEN  2048
#define HID    2048
#define NHEADS 16
#define HS     128
#define QKV_N  6144
#define KTOT   2048
#define INV_NORM 0.08838834764831845f

// ---------------- scratch (device globals; no allocations allowed) ----------
__device__ __half g_A[(size_t)S_LEN * HID];
__device__ __half g_Bq[(size_t)QKV_N * HID];
__device__ __half g_Bo[(size_t)HID * HID];
__device__ __half g_AT[(size_t)S_LEN * HID];
__device__ __half g_Qq[(size_t)NHEADS * S_LEN * HS];
__device__ __half g_Kk[(size_t)NHEADS * S_LEN * HS];
__device__ __half g_Vv[(size_t)NHEADS * S_LEN * HS];

__device__ __constant__ float c_invfreq[16] = {
    1.0f, 0.5623413251903491f, 0.31622776601683794f, 0.17782794100389228f,
    0.1f, 0.05623413251903491f, 0.03162277660168379f, 0.017782794100389228f,
    0.01f, 0.005623413251903491f, 0.0031622776601683794f, 0.0017782794100389228f,
    0.001f, 0.0005623413251903491f, 0.00031622776601683794f, 0.00017782794100389228f
};

// ------------------------------- helpers ------------------------------------
__device__ __forceinline__ uint32_t smem_to_u32(const void* p) {
    uint32_t a;
    asm("{ .reg .u64 t; cvta.to.shared.u64 t, %1; cvt.u32.u64 %0, t; }"
        : "=r"(a) : "l"(p));
    return a;
}
__device__ __forceinline__ void cp_async16(uint32_t dst, const void* src) {
    asm volatile("cp.async.cg.shared.global [%0], [%1], 16;"
                 :: "r"(dst), "l"(src) : "memory");
}
#define CP_COMMIT() asm volatile("cp.async.commit_group;" ::: "memory")
#define CP_WAIT(n)  asm volatile("cp.async.wait_group %0;" :: "n"(n) : "memory")

__device__ __forceinline__ void mma_f16(float* c, const uint32_t* a, const uint32_t* b) {
    asm volatile(
        "mma.sync.aligned.m16n8k16.row.col.f32.f16.f16.f32 "
        "{%0,%1,%2,%3}, {%4,%5,%6,%7}, {%8,%9}, {%0,%1,%2,%3};"
        : "+f"(c[0]), "+f"(c[1]), "+f"(c[2]), "+f"(c[3])
        : "r"(a[0]), "r"(a[1]), "r"(a[2]), "r"(a[3]), "r"(b[0]), "r"(b[1]));
}
__device__ __forceinline__ void ldsm4(uint32_t& r0, uint32_t& r1, uint32_t& r2,
                                      uint32_t& r3, uint32_t addr) {
    asm volatile("ldmatrix.sync.aligned.m8n8.x4.shared.b16 {%0,%1,%2,%3}, [%4];"
        : "=r"(r0), "=r"(r1), "=r"(r2), "=r"(r3) : "r"(addr));
}
__device__ __forceinline__ void ldsm4t(uint32_t& r0, uint32_t& r1, uint32_t& r2,
                                       uint32_t& r3, uint32_t addr) {
    asm volatile("ldmatrix.sync.aligned.m8n8.x4.trans.shared.b16 {%0,%1,%2,%3}, [%4];"
        : "=r"(r0), "=r"(r1), "=r"(r2), "=r"(r3) : "r"(addr));
}
__device__ __forceinline__ uint32_t packh(float lo, float hi) {
    uint32_t d;
    asm("cvt.rn.f16x2.f32 %0, %1, %2;" : "=r"(d) : "f"(hi), "f"(lo));
    return d;
}

// ---------------------------------------------------------------------------
// Conversion kernels
// ---------------------------------------------------------------------------
__global__ __launch_bounds__(256) void conv_h(
    const float4* __restrict__ X, __half2* __restrict__ H)
{
    int i = blockIdx.x * 256 + threadIdx.x;
    float4 v = X[i];
    H[2 * i]     = __halves2half2(__float2half_rn(v.x), __float2half_rn(v.y));
    H[2 * i + 1] = __halves2half2(__float2half_rn(v.z), __float2half_rn(v.w));
}

__global__ __launch_bounds__(256) void conv_transpose_h(
    const float* __restrict__ B, __half* __restrict__ H, int K, int N)
{
    __shared__ float t[32][33];
    int x = threadIdx.x & 31, y = threadIdx.x >> 5;
    int n0 = blockIdx.x * 32, k0 = blockIdx.y * 32;
#pragma unroll
    for (int j = 0; j < 32; j += 8)
        t[y + j][x] = B[(size_t)(k0 + y + j) * N + n0 + x];
    __syncthreads();
#pragma unroll
    for (int j = 0; j < 32; j += 8)
        H[(size_t)(n0 + y + j) * K + k0 + x] = __float2half_rn(t[x][y + j]);
}

// ---------------------------------------------------------------------------
// fp16 mma.sync GEMM (R13 shape): BM=64, BN=256, BK=32, 128 threads
// (4 warps, warp tile 64x64). 4-stage ring, ONE stage per iteration,
// CP_WAIT(2): prefetch depth = 2 full iterations of compute. 2 CTAs/SM.
// mode 0 epilogue: fused rotary + Q/K/V fp16 stores.
// ---------------------------------------------------------------------------
#define GBK 32
#define GNITER (KTOT / GBK)          // 64
#define ROWSTR 40
#define A_BUFH (64 * ROWSTR)         // 2560 halves
#define B_BUFH (256 * ROWSTR)        // 10240 halves
#define ST_A 0
#define ST_B A_BUFH
#define STGH  (A_BUFH + B_BUFH)      // 12800 halves = 25600 B
#define GSTAGES 4
#define GEMM_SMEM (GSTAGES * STGH * 2)    // 102400 B -> 2 CTAs/SM

__global__ __launch_bounds__(128, 2) void gemm_mma(
    const __half* __restrict__ A, const __half* __restrict__ Bw,
    const float* __restrict__ bias, int N, float* __restrict__ Cout, int mode)
{
    extern __shared__ __align__(16) __half sm[];
    const int tid = threadIdx.x;
    const int wn = tid >> 5, lane = tid & 31;
    const int n0 = blockIdx.x * 256, m0 = blockIdx.y * 64;
    const uint32_t sbase = smem_to_u32(sm);

    const int r  = lane >> 2;
    const int c2 = (lane & 3) * 2;
    const int arow = ((lane >> 3) & 1) * 8 + (lane & 7);
    const int acol = (lane >> 4) * 8;
    const int brow = ((lane >> 4) & 1) * 8 + (lane & 7);
    const int bcol = ((lane >> 3) & 1) * 8;

    float acc[4][8][4];
#pragma unroll
    for (int i = 0; i < 4; i++)
#pragma unroll
        for (int j = 0; j < 8; j++)
#pragma unroll
            for (int q = 0; q < 4; q++) acc[i][j][q] = 0.f;

    auto load_stage = [&](int s, int k0) {
        const uint32_t st = sbase + (uint32_t)s * STGH * 2;
#pragma unroll
        for (int i = 0; i < 2; i++) {               // A: 256 chunks
            int c = tid + i * 128;
            int row = c >> 2, kc = c & 3;
            uint32_t doff = (uint32_t)(row * ROWSTR + kc * 8) * 2;
            cp_async16(st + ST_A * 2 + doff,
                       A + (size_t)(m0 + row) * KTOT + k0 + kc * 8);
        }
#pragma unroll
        for (int i = 0; i < 8; i++) {               // B: 1024 chunks
            int c = tid + i * 128;
            int row = c >> 2, kc = c & 3;
            uint32_t doff = (uint32_t)(row * ROWSTR + kc * 8) * 2;
            cp_async16(st + ST_B * 2 + doff,
                       Bw + (size_t)(n0 + row) * KTOT + k0 + kc * 8);
        }
    };

    load_stage(0, 0);       CP_COMMIT();
    load_stage(1, GBK);     CP_COMMIT();
    load_stage(2, 2 * GBK); CP_COMMIT();

    for (int it = 0; it < GNITER; it++) {
        const int s = it & 3;
        if (it < GNITER - 1) { CP_WAIT(2); } else { CP_WAIT(0); }
        __syncthreads();

        const uint32_t stg = sbase + (uint32_t)s * STGH * 2;

#pragma unroll
        for (int ks = 0; ks < 2; ks++) {
            uint32_t ah[4][4], bh[8][2];
#pragma unroll
            for (int i = 0; i < 4; i++) {
                uint32_t a = stg + ST_A * 2
                           + (uint32_t)((i * 16 + arow) * ROWSTR + ks * 16 + acol) * 2;
                ldsm4(ah[i][0], ah[i][1], ah[i][2], ah[i][3], a);
            }
#pragma unroll
            for (int jp = 0; jp < 4; jp++) {
                uint32_t b = stg + ST_B * 2
                           + (uint32_t)((wn * 64 + jp * 16 + brow) * ROWSTR
                                        + ks * 16 + bcol) * 2;
                ldsm4(bh[jp * 2][0], bh[jp * 2][1],
                      bh[jp * 2 + 1][0], bh[jp * 2 + 1][1], b);
            }
#pragma unroll
            for (int i = 0; i < 4; i++)
#pragma unroll
                for (int j = 0; j < 8; j++) mma_f16(acc[i][j], ah[i], bh[j]);
        }
        // prefetch stage (it+3)%4 == (it-1)%4 — its readers all passed the
        // barrier at the top of this iteration; no extra barrier needed.
        if (it + 3 < GNITER) {
            load_stage((it + 3) & 3, (it + 3) * GBK);
            CP_COMMIT();
        }
    }

#pragma unroll
    for (int i = 0; i < 4; i++) {
#pragma unroll
        for (int j = 0; j < 8; j++) {
            int n = n0 + wn * 64 + j * 8 + c2;
            float2 bv = *reinterpret_cast<const float2*>(bias + n);
#pragma unroll
            for (int half = 0; half < 2; half++) {
                int m = m0 + i * 16 + r + half * 8;
                float2 v = make_float2(acc[i][j][half * 2] + bv.x,
                                       acc[i][j][half * 2 + 1] + bv.y);
                if (mode) {
                    *reinterpret_cast<float2*>(Cout + (size_t)m * N + n) = v;
                } else {
                    int h = n / 384, e = n - h * 384;
                    int seg = e >> 7, d = e & 127;
                    if (seg < 2 && d < 32) {   // fused rotary: partner acc[i][j±2]
                        bool low = d < 16;
                        int jp = low ? j + 2 : j - 2;
                        int np = low ? n + 16 : n - 16;
                        float2 bvp = *reinterpret_cast<const float2*>(bias + np);
                        float px = acc[i][jp][half * 2] + bvp.x;
                        float py = acc[i][jp][half * 2 + 1] + bvp.y;
                        float f0 = (float)m * c_invfreq[d & 15];
                        float f1 = (float)m * c_invfreq[(d + 1) & 15];
                        float s0, c0, s1, c1;
                        sincosf(f0, &s0, &c0);
                        sincosf(f1, &s1, &c1);
                        if (low) { v.x = v.x * c0 - px * s0; v.y = v.y * c1 - py * s1; }
                        else     { v.x = v.x * c0 + px * s0; v.y = v.y * c1 + py * s1; }
                    }
                    size_t off = ((size_t)h * S_LEN + m) * HS + d;
                    uint32_t hp = packh(v.x, v.y);
                    if (seg == 0)      *reinterpret_cast<uint32_t*>(g_Qq + off) = hp;
                    else if (seg == 1) *reinterpret_cast<uint32_t*>(g_Kk + off) = hp;
                    else               *reinterpret_cast<uint32_t*>(g_Vv + off) = hp;
                }
            }
        }
    }
}

// ---------------------------------------------------------------------------
// Flash attention, plain fp16 mma.sync (unchanged from R13).
// ---------------------------------------------------------------------------
#define KSTR 136
#define SM_K 0
#define SM_V (64 * KSTR)
#define FLASH_SMEM (2 * 64 * KSTR * 2)

__global__ __launch_bounds__(128, 2) void flash_mma()
{
    const int h  = blockIdx.y;
    const int qt = (gridDim.x - 1) - blockIdx.x;
    const int q0 = qt * 64;

    extern __shared__ __align__(16) __half fsm[];
    const uint32_t sbase = smem_to_u32(fsm);

    const int tid = threadIdx.x;
    const int w = tid >> 5, lane = tid & 31;
    const int r = lane >> 2, c2 = (lane & 3) * 2;
    const int brow = ((lane >> 4) & 1) * 8 + (lane & 7);
    const int bcol = ((lane >> 3) & 1) * 8;
    const int trow = lane & 15;
    const int tcol = ((lane >> 4) & 1) * 8;
    const int qrow = q0 + w * 16 + r;

    const __half* Qg = g_Qq + (size_t)h * S_LEN * HS;
    const __half* Kg = g_Kk + (size_t)h * S_LEN * HS;
    const __half* Vg = g_Vv + (size_t)h * S_LEN * HS;

    auto load_K = [&](int kt) {
        const int kb0 = kt * 64;
#pragma unroll
        for (int i = 0; i < 8; i++) {
            int c = i * 128 + tid;
            int row = c >> 4, col = c & 15;
            cp_async16(sbase + SM_K * 2 + (uint32_t)(row * KSTR + col * 8) * 2,
                       Kg + (size_t)(kb0 + row) * HS + col * 8);
        }
    };
    auto load_V = [&](int kt) {
        const int kb0 = kt * 64;
#pragma unroll
        for (int i = 0; i < 8; i++) {
            int c = i * 128 + tid;
            int row = c >> 4, col = c & 15;
            cp_async16(sbase + SM_V * 2 + (uint32_t)(row * KSTR + col * 8) * 2,
                       Vg + (size_t)(kb0 + row) * HS + col * 8);
        }
    };

    uint32_t qh[8][4];
#pragma unroll
    for (int kc = 0; kc < 8; kc++) {
        size_t o0 = (size_t)qrow * HS + kc * 16 + c2;
        size_t o1 = (size_t)(qrow + 8) * HS + kc * 16 + c2;
        qh[kc][0] = *reinterpret_cast<const uint32_t*>(Qg + o0);
        qh[kc][1] = *reinterpret_cast<const uint32_t*>(Qg + o1);
        qh[kc][2] = *reinterpret_cast<const uint32_t*>(Qg + o0 + 8);
        qh[kc][3] = *reinterpret_cast<const uint32_t*>(Qg + o1 + 8);
    }

    load_K(0); CP_COMMIT();
    load_V(0); CP_COMMIT();

    float o[16][4];
#pragma unroll
    for (int t = 0; t < 16; t++)
#pragma unroll
        for (int q = 0; q < 4; q++) o[t][q] = 0.f;
    float m2[2] = {-1e30f, -1e30f};
    float l[2] = {0.f, 0.f};

    const float SC = INV_NORM * 1.4426950408889634f;

    for (int kt = 0; kt <= qt; kt++) {
        const int kb0 = kt * 64;
        CP_WAIT(1);
        __syncthreads();

        float sacc[8][4];
#pragma unroll
        for (int j = 0; j < 8; j++)
#pragma unroll
            for (int q = 0; q < 4; q++) sacc[j][q] = 0.f;
#pragma unroll
        for (int kc = 0; kc < 8; kc++) {
#pragma unroll
            for (int jh = 0; jh < 2; jh++) {
                uint32_t bh[4][2];
#pragma unroll
                for (int jp = 0; jp < 2; jp++) {
                    uint32_t a = sbase + SM_K * 2
                        + (uint32_t)(((jh * 4 + jp * 2) * 8 + brow) * KSTR
                                     + kc * 16 + bcol) * 2;
                    ldsm4(bh[jp * 2][0], bh[jp * 2][1],
                          bh[jp * 2 + 1][0], bh[jp * 2 + 1][1], a);
                }
#pragma unroll
                for (int jj = 0; jj < 4; jj++) mma_f16(sacc[jh * 4 + jj], qh[kc], bh[jj]);
            }
        }

        if (kt == qt) {
#pragma unroll
            for (int j = 0; j < 8; j++) {
#pragma unroll
                for (int q = 0; q < 4; q++) {
                    int col = kb0 + j * 8 + c2 + (q & 1);
                    int row = qrow + ((q >= 2) ? 8 : 0);
                    if (col > row) sacc[j][q] = -1e30f;
                }
            }
        }

#pragma unroll
        for (int g = 0; g < 2; g++) {
            float rm = -1e30f;
#pragma unroll
            for (int j = 0; j < 8; j++)
                rm = fmaxf(rm, fmaxf(sacc[j][2 * g], sacc[j][2 * g + 1]));
            rm *= SC;
            rm = fmaxf(rm, __shfl_xor_sync(0xffffffffu, rm, 1));
            rm = fmaxf(rm, __shfl_xor_sync(0xffffffffu, rm, 2));
            float mn = fmaxf(m2[g], rm);
            float alpha = exp2f(m2[g] - mn);
            m2[g] = mn;
            float rs = 0.f;
#pragma unroll
            for (int j = 0; j < 8; j++) {
#pragma unroll
                for (int q = 2 * g; q < 2 * g + 2; q++) {
                    float p = exp2f(sacc[j][q] * SC - mn);
                    sacc[j][q] = p;
                    rs += p;
                }
            }
            rs += __shfl_xor_sync(0xffffffffu, rs, 1);
            rs += __shfl_xor_sync(0xffffffffu, rs, 2);
            l[g] = l[g] * alpha + rs;
#pragma unroll
            for (int t = 0; t < 16; t++) {
                o[t][2 * g]     *= alpha;
                o[t][2 * g + 1] *= alpha;
            }
        }

        __syncthreads();
        const bool more = (kt + 1 <= qt);
        if (more) { load_K(kt + 1); CP_COMMIT(); CP_WAIT(1); }
        else      { CP_WAIT(0); }
        __syncthreads();

#pragma unroll
        for (int kc2 = 0; kc2 < 4; kc2++) {
            uint32_t ph[4];
            ph[0] = packh(sacc[2 * kc2][0], sacc[2 * kc2][1]);
            ph[1] = packh(sacc[2 * kc2][2], sacc[2 * kc2][3]);
            ph[2] = packh(sacc[2 * kc2 + 1][0], sacc[2 * kc2 + 1][1]);
            ph[3] = packh(sacc[2 * kc2 + 1][2], sacc[2 * kc2 + 1][3]);
#pragma unroll
            for (int jg = 0; jg < 8; jg++) {
                uint32_t a = sbase + SM_V * 2
                    + (uint32_t)((kc2 * 16 + trow) * KSTR + jg * 16 + tcol) * 2;
                uint32_t vh[2][2];
                ldsm4t(vh[0][0], vh[0][1], vh[1][0], vh[1][1], a);
#pragma unroll
                for (int jj = 0; jj < 2; jj++) mma_f16(o[jg * 2 + jj], ph, vh[jj]);
            }
        }

        if (more) {
            __syncthreads();
            load_V(kt + 1); CP_COMMIT();
        }
    }

    float inv0 = 1.f / l[0], inv1 = 1.f / l[1];
#pragma unroll
    for (int jd = 0; jd < 16; jd++) {
        int col = h * HS + jd * 8 + c2;
        *reinterpret_cast<uint32_t*>(g_AT + (size_t)qrow * HID + col) =
            packh(o[jd][0] * inv0, o[jd][1] * inv0);
        *reinterpret_cast<uint32_t*>(g_AT + (size_t)(qrow + 8) * HID + col) =
            packh(o[jd][2] * inv1, o[jd][3] * inv1);
    }
}

// ---------------------------------------------------------------------------
extern "C" void kernel_launch(void* const* d_in, const int* in_sizes, int n_in,
                              void* d_out, int out_size)
{
    (void)in_sizes; (void)n_in; (void)out_size;
    const float* hidden = (const float*)d_in[0];
    const float* qkvk = (const float*)d_in[2];
    const float* qkvb = (const float*)d_in[3];
    const float* outk = (const float*)d_in[4];
    const float* outb = (const float*)d_in[5];
    float* out = (float*)d_out;

    cudaFuncSetAttribute(gemm_mma, cudaFuncAttributeMaxDynamicSharedMemorySize, GEMM_SMEM);
    cudaFuncSetAttribute(flash_mma, cudaFuncAttributeMaxDynamicSharedMemorySize, FLASH_SMEM);

    void *A, *Bq, *Bo, *AT;
    cudaGetSymbolAddress(&A, g_A);
    cudaGetSymbolAddress(&Bq, g_Bq);   cudaGetSymbolAddress(&Bo, g_Bo);
    cudaGetSymbolAddress(&AT, g_AT);

    conv_h<<<(S_LEN * HID) / 1024, 256>>>((const float4*)hidden, (__half2*)A);
    conv_transpose_h<<<dim3(QKV_N / 32, HID / 32), 256>>>(
        qkvk, (__half*)Bq, HID, QKV_N);
    conv_transpose_h<<<dim3(HID / 32, HID / 32), 256>>>(
        outk, (__half*)Bo, HID, HID);

    // QKV projection + fused rotary; Q/K/V fp16
    gemm_mma<<<dim3(QKV_N / 256, S_LEN / 64), 128, GEMM_SMEM>>>(
        (const __half*)A, (const __half*)Bq, qkvb, QKV_N, nullptr, 0);

    // causal flash attention
    flash_mma<<<dim3(S_LEN / 64, NHEADS), 128, FLASH_SMEM>>>();

    // output projection
    gemm_mma<<<dim3(HID / 256, S_LEN / 64), 128, GEMM_SMEM>>>(
        (const __half*)AT, (const __half*)Bo, outb, HID, out, 1);
}

// round 17
// speedup vs baseline: 1.7984x; 1.0528x over previous
#include <cuda_runtime.h>
#include <cuda_fp16.h>
#include <math.h>
#include <stdint.h>

#define S_LEN  2048
#define HID    2048
#define NHEADS 16
#define HS     128
#define QKV_N  6144
#define KTOT   2048
#define INV_NORM 0.08838834764831845f

// ---------------- scratch (device globals; no allocations allowed) ----------
__device__ __half g_A[(size_t)S_LEN * HID];        // hidden fp16 [m][k]
__device__ __half g_Bq[(size_t)KTOT * QKV_N];      // qkv kernel fp16 [k][n] (native)
__device__ __half g_Bo[(size_t)KTOT * HID];        // out kernel fp16 [k][n] (native)
__device__ __half g_AT[(size_t)S_LEN * HID];       // attn out fp16 [m][k]
__device__ __half g_Qq[(size_t)NHEADS * S_LEN * HS];
__device__ __half g_Kk[(size_t)NHEADS * S_LEN * HS];
__device__ __half g_Vv[(size_t)NHEADS * S_LEN * HS];

__device__ __constant__ float c_invfreq[16] = {
    1.0f, 0.5623413251903491f, 0.31622776601683794f, 0.17782794100389228f,
    0.1f, 0.05623413251903491f, 0.03162277660168379f, 0.017782794100389228f,
    0.01f, 0.005623413251903491f, 0.0031622776601683794f, 0.0017782794100389228f,
    0.001f, 0.0005623413251903491f, 0.00031622776601683794f, 0.00017782794100389228f
};

// ------------------------------- helpers ------------------------------------
__device__ __forceinline__ uint32_t smem_to_u32(const void* p) {
    uint32_t a;
    asm("{ .reg .u64 t; cvta.to.shared.u64 t, %1; cvt.u32.u64 %0, t; }"
        : "=r"(a) : "l"(p));
    return a;
}
__device__ __forceinline__ void cp_async16(uint32_t dst, const void* src) {
    asm volatile("cp.async.cg.shared.global [%0], [%1], 16;"
                 :: "r"(dst), "l"(src) : "memory");
}
#define CP_COMMIT() asm volatile("cp.async.commit_group;" ::: "memory")
#define CP_WAIT(n)  asm volatile("cp.async.wait_group %0;" :: "n"(n) : "memory")

__device__ __forceinline__ void mma_f16(float* c, const uint32_t* a, const uint32_t* b) {
    asm volatile(
        "mma.sync.aligned.m16n8k16.row.col.f32.f16.f16.f32 "
        "{%0,%1,%2,%3}, {%4,%5,%6,%7}, {%8,%9}, {%0,%1,%2,%3};"
        : "+f"(c[0]), "+f"(c[1]), "+f"(c[2]), "+f"(c[3])
        : "r"(a[0]), "r"(a[1]), "r"(a[2]), "r"(a[3]), "r"(b[0]), "r"(b[1]));
}
__device__ __forceinline__ void ldsm4(uint32_t& r0, uint32_t& r1, uint32_t& r2,
                                      uint32_t& r3, uint32_t addr) {
    asm volatile("ldmatrix.sync.aligned.m8n8.x4.shared.b16 {%0,%1,%2,%3}, [%4];"
        : "=r"(r0), "=r"(r1), "=r"(r2), "=r"(r3) : "r"(addr));
}
__device__ __forceinline__ void ldsm4t(uint32_t& r0, uint32_t& r1, uint32_t& r2,
                                       uint32_t& r3, uint32_t addr) {
    asm volatile("ldmatrix.sync.aligned.m8n8.x4.trans.shared.b16 {%0,%1,%2,%3}, [%4];"
        : "=r"(r0), "=r"(r1), "=r"(r2), "=r"(r3) : "r"(addr));
}
__device__ __forceinline__ uint32_t packh(float lo, float hi) {
    uint32_t d;
    asm("cvt.rn.f16x2.f32 %0, %1, %2;" : "=r"(d) : "f"(hi), "f"(lo));
    return d;
}

// ---------------------------------------------------------------------------
// Conversion: plain fp32 -> fp16 streaming copy (no transpose needed anymore)
// ---------------------------------------------------------------------------
__global__ __launch_bounds__(256) void conv_h(
    const float4* __restrict__ X, __half2* __restrict__ H)
{
    int i = blockIdx.x * 256 + threadIdx.x;
    float4 v = X[i];
    H[2 * i]     = __halves2half2(__float2half_rn(v.x), __float2half_rn(v.y));
    H[2 * i + 1] = __halves2half2(__float2half_rn(v.z), __float2half_rn(v.w));
}

// ---------------------------------------------------------------------------
// fp16 mma.sync GEMM: C[M,N] = A[M,K] * B[K,N] + bias.
// A K-major (ldmatrix), B native [k][n] in smem pitch 264 -> ldmatrix.trans.
// BM=64, BN=256, BK=32, 128 threads (warp tile 64x64),
// 4-stage ring with CP_WAIT(2) (prefetch depth 2 iters), 2 CTAs/SM.
// mode 0 epilogue: fused rotary + Q/K/V fp16 stores.
// ---------------------------------------------------------------------------
#define GBK 32
#define GNITER (KTOT / GBK)          // 64
#define ROWSTR 40                    // A tile pitch (halves)
#define NSTR 264                     // B tile pitch (halves): 132 words, %32==4
#define A_BUFH (64 * ROWSTR)         // 2560 halves
#define B_BUFH (GBK * NSTR)          // 8448 halves
#define ST_A 0
#define ST_B A_BUFH
#define STGH  (A_BUFH + B_BUFH)      // 11008 halves = 22016 B
#define GSTAGES 4
#define GEMM_SMEM (GSTAGES * STGH * 2)    // 88064 B -> 2 CTAs/SM

__global__ __launch_bounds__(128, 2) void gemm_mma(
    const __half* __restrict__ A, const __half* __restrict__ Bw,
    const float* __restrict__ bias, int N, float* __restrict__ Cout, int mode)
{
    extern __shared__ __align__(16) __half sm[];
    const int tid = threadIdx.x;
    const int wn = tid >> 5, lane = tid & 31;
    const int n0 = blockIdx.x * 256, m0 = blockIdx.y * 64;
    const uint32_t sbase = smem_to_u32(sm);

    const int r  = lane >> 2;
    const int c2 = (lane & 3) * 2;
    const int arow = ((lane >> 3) & 1) * 8 + (lane & 7);
    const int acol = (lane >> 4) * 8;
    const int trow = lane & 15;                 // trans-ldsm k-row
    const int tcol = ((lane >> 4) & 1) * 8;     // trans-ldsm n-col half

    float acc[4][8][4];
#pragma unroll
    for (int i = 0; i < 4; i++)
#pragma unroll
        for (int j = 0; j < 8; j++)
#pragma unroll
            for (int q = 0; q < 4; q++) acc[i][j][q] = 0.f;

    auto load_stage = [&](int s, int k0) {
        const uint32_t st = sbase + (uint32_t)s * STGH * 2;
#pragma unroll
        for (int i = 0; i < 2; i++) {               // A: 256 chunks (K-major)
            int c = tid + i * 128;
            int row = c >> 2, kc = c & 3;
            uint32_t doff = (uint32_t)(row * ROWSTR + kc * 8) * 2;
            cp_async16(st + ST_A * 2 + doff,
                       A + (size_t)(m0 + row) * KTOT + k0 + kc * 8);
        }
#pragma unroll
        for (int i = 0; i < 8; i++) {               // B: 1024 chunks ([k][n] rows)
            int c = tid + i * 128;
            int row = c >> 5, ch = c & 31;          // 32 rows x 32 chunks
            uint32_t doff = (uint32_t)(row * NSTR + ch * 8) * 2;
            cp_async16(st + ST_B * 2 + doff,
                       Bw + (size_t)(k0 + row) * N + n0 + ch * 8);
        }
    };

    load_stage(0, 0);       CP_COMMIT();
    load_stage(1, GBK);     CP_COMMIT();
    load_stage(2, 2 * GBK); CP_COMMIT();

    for (int it = 0; it < GNITER; it++) {
        const int s = it & 3;
        if (it < GNITER - 1) { CP_WAIT(2); } else { CP_WAIT(0); }
        __syncthreads();

        const uint32_t stg = sbase + (uint32_t)s * STGH * 2;

#pragma unroll
        for (int ks = 0; ks < 2; ks++) {
            uint32_t ah[4][4], bh[8][2];
#pragma unroll
            for (int i = 0; i < 4; i++) {
                uint32_t a = stg + ST_A * 2
                           + (uint32_t)((i * 16 + arow) * ROWSTR + ks * 16 + acol) * 2;
                ldsm4(ah[i][0], ah[i][1], ah[i][2], ah[i][3], a);
            }
#pragma unroll
            for (int jg = 0; jg < 4; jg++) {        // B via trans-ldsm from [k][n]
                uint32_t b = stg + ST_B * 2
                           + (uint32_t)((ks * 16 + trow) * NSTR
                                        + wn * 64 + jg * 16 + tcol) * 2;
                ldsm4t(bh[jg * 2][0], bh[jg * 2][1],
                       bh[jg * 2 + 1][0], bh[jg * 2 + 1][1], b);
            }
#pragma unroll
            for (int i = 0; i < 4; i++)
#pragma unroll
                for (int j = 0; j < 8; j++) mma_f16(acc[i][j], ah[i], bh[j]);
        }
        if (it + 3 < GNITER) {
            load_stage((it + 3) & 3, (it + 3) * GBK);
            CP_COMMIT();
        }
    }

#pragma unroll
    for (int i = 0; i < 4; i++) {
#pragma unroll
        for (int j = 0; j < 8; j++) {
            int n = n0 + wn * 64 + j * 8 + c2;
            float2 bv = *reinterpret_cast<const float2*>(bias + n);
#pragma unroll
            for (int half = 0; half < 2; half++) {
                int m = m0 + i * 16 + r + half * 8;
                float2 v = make_float2(acc[i][j][half * 2] + bv.x,
                                       acc[i][j][half * 2 + 1] + bv.y);
                if (mode) {
                    *reinterpret_cast<float2*>(Cout + (size_t)m * N + n) = v;
                } else {
                    int h = n / 384, e = n - h * 384;
                    int seg = e >> 7, d = e & 127;
                    if (seg < 2 && d < 32) {   // fused rotary: partner acc[i][j±2]
                        bool low = d < 16;
                        int jp = low ? j + 2 : j - 2;
                        int np = low ? n + 16 : n - 16;
                        float2 bvp = *reinterpret_cast<const float2*>(bias + np);
                        float px = acc[i][jp][half * 2] + bvp.x;
                        float py = acc[i][jp][half * 2 + 1] + bvp.y;
                        float f0 = (float)m * c_invfreq[d & 15];
                        float f1 = (float)m * c_invfreq[(d + 1) & 15];
                        float s0, c0, s1, c1;
                        sincosf(f0, &s0, &c0);
                        sincosf(f1, &s1, &c1);
                        if (low) { v.x = v.x * c0 - px * s0; v.y = v.y * c1 - py * s1; }
                        else     { v.x = v.x * c0 + px * s0; v.y = v.y * c1 + py * s1; }
                    }
                    size_t off = ((size_t)h * S_LEN + m) * HS + d;
                    uint32_t hp = packh(v.x, v.y);
                    if (seg == 0)      *reinterpret_cast<uint32_t*>(g_Qq + off) = hp;
                    else if (seg == 1) *reinterpret_cast<uint32_t*>(g_Kk + off) = hp;
                    else               *reinterpret_cast<uint32_t*>(g_Vv + off) = hp;
                }
            }
        }
    }
}

// ---------------------------------------------------------------------------
// Flash attention, plain fp16 mma.sync (unchanged from R16).
// ---------------------------------------------------------------------------
#define KSTR 136
#define SM_K 0
#define SM_V (64 * KSTR)
#define FLASH_SMEM (2 * 64 * KSTR * 2)

__global__ __launch_bounds__(128, 2) void flash_mma()
{
    const int h  = blockIdx.y;
    const int qt = (gridDim.x - 1) - blockIdx.x;
    const int q0 = qt * 64;

    extern __shared__ __align__(16) __half fsm[];
    const uint32_t sbase = smem_to_u32(fsm);

    const int tid = threadIdx.x;
    const int w = tid >> 5, lane = tid & 31;
    const int r = lane >> 2, c2 = (lane & 3) * 2;
    const int brow = ((lane >> 4) & 1) * 8 + (lane & 7);
    const int bcol = ((lane >> 3) & 1) * 8;
    const int trow = lane & 15;
    const int tcol = ((lane >> 4) & 1) * 8;
    const int qrow = q0 + w * 16 + r;

    const __half* Qg = g_Qq + (size_t)h * S_LEN * HS;
    const __half* Kg = g_Kk + (size_t)h * S_LEN * HS;
    const __half* Vg = g_Vv + (size_t)h * S_LEN * HS;

    auto load_K = [&](int kt) {
        const int kb0 = kt * 64;
#pragma unroll
        for (int i = 0; i < 8; i++) {
            int c = i * 128 + tid;
            int row = c >> 4, col = c & 15;
            cp_async16(sbase + SM_K * 2 + (uint32_t)(row * KSTR + col * 8) * 2,
                       Kg + (size_t)(kb0 + row) * HS + col * 8);
        }
    };
    auto load_V = [&](int kt) {
        const int kb0 = kt * 64;
#pragma unroll
        for (int i = 0; i < 8; i++) {
            int c = i * 128 + tid;
            int row = c >> 4, col = c & 15;
            cp_async16(sbase + SM_V * 2 + (uint32_t)(row * KSTR + col * 8) * 2,
                       Vg + (size_t)(kb0 + row) * HS + col * 8);
        }
    };

    uint32_t qh[8][4];
#pragma unroll
    for (int kc = 0; kc < 8; kc++) {
        size_t o0 = (size_t)qrow * HS + kc * 16 + c2;
        size_t o1 = (size_t)(qrow + 8) * HS + kc * 16 + c2;
        qh[kc][0] = *reinterpret_cast<const uint32_t*>(Qg + o0);
        qh[kc][1] = *reinterpret_cast<const uint32_t*>(Qg + o1);
        qh[kc][2] = *reinterpret_cast<const uint32_t*>(Qg + o0 + 8);
        qh[kc][3] = *reinterpret_cast<const uint32_t*>(Qg + o1 + 8);
    }

    load_K(0); CP_COMMIT();
    load_V(0); CP_COMMIT();

    float o[16][4];
#pragma unroll
    for (int t = 0; t < 16; t++)
#pragma unroll
        for (int q = 0; q < 4; q++) o[t][q] = 0.f;
    float m2[2] = {-1e30f, -1e30f};
    float l[2] = {0.f, 0.f};

    const float SC = INV_NORM * 1.4426950408889634f;

    for (int kt = 0; kt <= qt; kt++) {
        const int kb0 = kt * 64;
        CP_WAIT(1);
        __syncthreads();

        float sacc[8][4];
#pragma unroll
        for (int j = 0; j < 8; j++)
#pragma unroll
            for (int q = 0; q < 4; q++) sacc[j][q] = 0.f;
#pragma unroll
        for (int kc = 0; kc < 8; kc++) {
#pragma unroll
            for (int jh = 0; jh < 2; jh++) {
                uint32_t bh[4][2];
#pragma unroll
                for (int jp = 0; jp < 2; jp++) {
                    uint32_t a = sbase + SM_K * 2
                        + (uint32_t)(((jh * 4 + jp * 2) * 8 + brow) * KSTR
                                     + kc * 16 + bcol) * 2;
                    ldsm4(bh[jp * 2][0], bh[jp * 2][1],
                          bh[jp * 2 + 1][0], bh[jp * 2 + 1][1], a);
                }
#pragma unroll
                for (int jj = 0; jj < 4; jj++) mma_f16(sacc[jh * 4 + jj], qh[kc], bh[jj]);
            }
        }

        if (kt == qt) {
#pragma unroll
            for (int j = 0; j < 8; j++) {
#pragma unroll
                for (int q = 0; q < 4; q++) {
                    int col = kb0 + j * 8 + c2 + (q & 1);
                    int row = qrow + ((q >= 2) ? 8 : 0);
                    if (col > row) sacc[j][q] = -1e30f;
                }
            }
        }

#pragma unroll
        for (int g = 0; g < 2; g++) {
            float rm = -1e30f;
#pragma unroll
            for (int j = 0; j < 8; j++)
                rm = fmaxf(rm, fmaxf(sacc[j][2 * g], sacc[j][2 * g + 1]));
            rm *= SC;
            rm = fmaxf(rm, __shfl_xor_sync(0xffffffffu, rm, 1));
            rm = fmaxf(rm, __shfl_xor_sync(0xffffffffu, rm, 2));
            float mn = fmaxf(m2[g], rm);
            float alpha = exp2f(m2[g] - mn);
            m2[g] = mn;
            float rs = 0.f;
#pragma unroll
            for (int j = 0; j < 8; j++) {
#pragma unroll
                for (int q = 2 * g; q < 2 * g + 2; q++) {
                    float p = exp2f(sacc[j][q] * SC - mn);
                    sacc[j][q] = p;
                    rs += p;
                }
            }
            rs += __shfl_xor_sync(0xffffffffu, rs, 1);
            rs += __shfl_xor_sync(0xffffffffu, rs, 2);
            l[g] = l[g] * alpha + rs;
#pragma unroll
            for (int t = 0; t < 16; t++) {
                o[t][2 * g]     *= alpha;
                o[t][2 * g + 1] *= alpha;
            }
        }

        __syncthreads();
        const bool more = (kt + 1 <= qt);
        if (more) { load_K(kt + 1); CP_COMMIT(); CP_WAIT(1); }
        else      { CP_WAIT(0); }
        __syncthreads();

#pragma unroll
        for (int kc2 = 0; kc2 < 4; kc2++) {
            uint32_t ph[4];
            ph[0] = packh(sacc[2 * kc2][0], sacc[2 * kc2][1]);
            ph[1] = packh(sacc[2 * kc2][2], sacc[2 * kc2][3]);
            ph[2] = packh(sacc[2 * kc2 + 1][0], sacc[2 * kc2 + 1][1]);
            ph[3] = packh(sacc[2 * kc2 + 1][2], sacc[2 * kc2 + 1][3]);
#pragma unroll
            for (int jg = 0; jg < 8; jg++) {
                uint32_t a = sbase + SM_V * 2
                    + (uint32_t)((kc2 * 16 + trow) * KSTR + jg * 16 + tcol) * 2;
                uint32_t vh[2][2];
                ldsm4t(vh[0][0], vh[0][1], vh[1][0], vh[1][1], a);
#pragma unroll
                for (int jj = 0; jj < 2; jj++) mma_f16(o[jg * 2 + jj], ph, vh[jj]);
            }
        }

        if (more) {
            __syncthreads();
            load_V(kt + 1); CP_COMMIT();
        }
    }

    float inv0 = 1.f / l[0], inv1 = 1.f / l[1];
#pragma unroll
    for (int jd = 0; jd < 16; jd++) {
        int col = h * HS + jd * 8 + c2;
        *reinterpret_cast<uint32_t*>(g_AT + (size_t)qrow * HID + col) =
            packh(o[jd][0] * inv0, o[jd][1] * inv0);
        *reinterpret_cast<uint32_t*>(g_AT + (size_t)(qrow + 8) * HID + col) =
            packh(o[jd][2] * inv1, o[jd][3] * inv1);
    }
}

// ---------------------------------------------------------------------------
extern "C" void kernel_launch(void* const* d_in, const int* in_sizes, int n_in,
                              void* d_out, int out_size)
{
    (void)in_sizes; (void)n_in; (void)out_size;
    const float* hidden = (const float*)d_in[0];
    const float* qkvk = (const float*)d_in[2];
    const float* qkvb = (const float*)d_in[3];
    const float* outk = (const float*)d_in[4];
    const float* outb = (const float*)d_in[5];
    float* out = (float*)d_out;

    cudaFuncSetAttribute(gemm_mma, cudaFuncAttributeMaxDynamicSharedMemorySize, GEMM_SMEM);
    cudaFuncSetAttribute(flash_mma, cudaFuncAttributeMaxDynamicSharedMemorySize, FLASH_SMEM);

    void *A, *Bq, *Bo, *AT;
    cudaGetSymbolAddress(&A, g_A);
    cudaGetSymbolAddress(&Bq, g_Bq);   cudaGetSymbolAddress(&Bo, g_Bo);
    cudaGetSymbolAddress(&AT, g_AT);

    // streaming fp32 -> fp16 copies (no transposes: B stays [k][n])
    conv_h<<<(S_LEN * HID) / 1024, 256>>>((const float4*)hidden, (__half2*)A);
    conv_h<<<(KTOT * QKV_N) / 1024, 256>>>((const float4*)qkvk, (__half2*)Bq);
    conv_h<<<(KTOT * HID) / 1024, 256>>>((const float4*)outk, (__half2*)Bo);

    // QKV projection + fused rotary; Q/K/V fp16
    gemm_mma<<<dim3(QKV_N / 256, S_LEN / 64), 128, GEMM_SMEM>>>(
        (const __half*)A, (const __half*)Bq, qkvb, QKV_N, nullptr, 0);

    // causal flash attention
    flash_mma<<<dim3(S_LEN / 64, NHEADS), 128, FLASH_SMEM>>>();

    // output projection
    gemm_mma<<<dim3(HID / 256, S_LEN / 64), 128, GEMM_SMEM>>>(
        (const __half*)AT, (const __half*)Bo, outb, HID, out, 1);
}